// round 9
// baseline (speedup 1.0000x reference)
#include <cuda_runtime.h>
#include <math.h>

#define BB 8
#define CC 256
#define HH 56
#define WW 56
#define HW (HH*WW)          // 3136
#define KK 3
#define TAPS 9
#define MID 51
#define CKK (CC*TAPS)       // 2304
#define GAIN_OVER_K 0.4714045207910317f   // sqrt(2)/3

__device__ float g_pooled[BB * CC];
__device__ float g_sf[BB * TAPS * HW];
__device__ float g_cf[BB * CKK];

typedef unsigned long long ull;

// ---- f32x2 packed helpers (sm_103a) --------------------------------------
__device__ __forceinline__ ull pack2(float x, float y) {
    ull r; asm("mov.b64 %0, {%1, %2};" : "=l"(r) : "f"(x), "f"(y)); return r;
}
__device__ __forceinline__ void unpack2(ull v, float& x, float& y) {
    asm("mov.b64 {%0, %1}, %2;" : "=f"(x), "=f"(y) : "l"(v));
}
__device__ __forceinline__ ull mul2(ull a, ull b) {
    ull d; asm("mul.rn.f32x2 %0, %1, %2;" : "=l"(d) : "l"(a), "l"(b)); return d;
}
__device__ __forceinline__ ull fma2(ull a, ull b, ull c) {
    ull d; asm("fma.rn.f32x2 %0, %1, %2, %3;" : "=l"(d) : "l"(a), "l"(b), "l"(c)); return d;
}

// ---- PDL intrinsics -------------------------------------------------------
__device__ __forceinline__ void gdc_launch_dependents() {
    asm volatile("griddepcontrol.launch_dependents;");
}
__device__ __forceinline__ void gdc_wait() {
    asm volatile("griddepcontrol.wait;" ::: "memory");
}

// ---------------------------------------------------------------------------
// Kernel A (R6 proven form): bx < 98 -> sf; bx >= 98 -> pooled means.
// ---------------------------------------------------------------------------
__global__ void __launch_bounds__(512, 4) kA_sf_pool(
    const float* __restrict__ x,
    const float* __restrict__ ws,
    const float* __restrict__ bs)
{
    __shared__ float ws_s[CC * 12];           // 12 KB
    __shared__ float red[16 * TAPS * 32];     // 18 KB

    gdc_launch_dependents();                  // let k2 start staging early

    const int b    = blockIdx.y;
    const int bx   = blockIdx.x;
    const int tid  = threadIdx.x;
    const int lane = tid & 31;
    const int w    = tid >> 5;

    if (bx >= 98) {
        const int c = (bx - 98) * 16 + w;
        const float4* p4 = (const float4*)(x + ((size_t)b * CC + c) * HW);
        float s = 0.f;
        for (int j = lane; j < 784; j += 32) {
            float4 v = __ldg(p4 + j);
            s += (v.x + v.y) + (v.z + v.w);
        }
#pragma unroll
        for (int o = 16; o > 0; o >>= 1) s += __shfl_xor_sync(0xffffffffu, s, o);
        if (lane == 0) g_pooled[b * CC + c] = s * (1.f / (float)HW);
        return;
    }

#pragma unroll
    for (int i = tid; i < TAPS * CC; i += 512) {
        int n = i >> 8, c = i & 255;
        ws_s[c * 12 + n] = ws[i];
    }
    __syncthreads();

    const int pix = bx * 32 + lane;
    const float* xb = x + ((size_t)b * CC + w * 16) * HW + pix;

    float acc[TAPS];
#pragma unroll
    for (int n = 0; n < TAPS; n++) acc[n] = 0.f;

#pragma unroll
    for (int cc = 0; cc < 16; cc++) {
        float xv = __ldg(xb + (size_t)cc * HW);
        const float* wr = ws_s + (w * 16 + cc) * 12;
        float4 wa = *(const float4*)(wr);
        float4 wb = *(const float4*)(wr + 4);
        float  w8 = wr[8];
        acc[0] = fmaf(xv, wa.x, acc[0]);
        acc[1] = fmaf(xv, wa.y, acc[1]);
        acc[2] = fmaf(xv, wa.z, acc[2]);
        acc[3] = fmaf(xv, wa.w, acc[3]);
        acc[4] = fmaf(xv, wb.x, acc[4]);
        acc[5] = fmaf(xv, wb.y, acc[5]);
        acc[6] = fmaf(xv, wb.z, acc[6]);
        acc[7] = fmaf(xv, wb.w, acc[7]);
        acc[8] = fmaf(xv, w8,   acc[8]);
    }

#pragma unroll
    for (int n = 0; n < TAPS; n++)
        red[(w * TAPS + n) * 32 + lane] = acc[n];
    __syncthreads();

    if (tid < 32) {
        float a[TAPS];
        float m = 0.f;
#pragma unroll
        for (int n = 0; n < TAPS; n++) {
            float s = 0.f;
#pragma unroll
            for (int gg = 0; gg < 16; gg++) s += red[(gg * TAPS + n) * 32 + tid];
            a[n] = s + __ldg(bs + n);
            m += a[n];
        }
        m *= (1.f / 9.f);
        float ss = 0.f;
#pragma unroll
        for (int n = 0; n < TAPS; n++) { float d = a[n] - m; ss = fmaf(d, d, ss); }
        float inv = GAIN_OVER_K / (sqrtf(ss * (1.f / 8.f)) + 1e-10f);
        const int pix2 = bx * 32 + tid;
#pragma unroll
        for (int n = 0; n < TAPS; n++)
            g_sf[((size_t)b * TAPS + n) * HW + pix2] = (a[n] - m) * inv;
    }
}

// ---------------------------------------------------------------------------
// Kernel 2: PDL secondary. Stage w2 (independent) BEFORE gdc_wait, then MLP.
// ---------------------------------------------------------------------------
__global__ void __launch_bounds__(256) k2_mlp_cf(
    const float* __restrict__ w1, const float* __restrict__ b1,
    const float* __restrict__ w2, const float* __restrict__ b2,
    const float* __restrict__ fn_std)
{
    __shared__ float pooled_s[CC];
    __shared__ float y1_s[52];
    __shared__ float w2c[144 * MID];
    __shared__ float y2_s[144];

    const int cg   = blockIdx.x;
    const int b    = blockIdx.y;
    const int tid  = threadIdx.x;
    const int warp = tid >> 5;
    const int lane = tid & 31;

    gdc_launch_dependents();                  // let k3 start its x loads early

    // stage w2 chunk — depends only on input w2, overlap with kA
    {
        const float4* src = (const float4*)(w2 + (size_t)cg * 144 * MID);
#pragma unroll
        for (int i = tid; i < 144 * MID / 4; i += 256)
            ((float4*)w2c)[i] = __ldg(src + i);
    }

    gdc_wait();                               // kA's g_pooled now visible
    pooled_s[tid] = g_pooled[b * CC + tid];
    __syncthreads();

    for (int j = warp; j < MID; j += 8) {
        const float* wr = w1 + j * CC;
        float s = 0.f;
#pragma unroll
        for (int k = 0; k < CC / 32; k++)
            s = fmaf(pooled_s[lane + k * 32], __ldg(wr + lane + k * 32), s);
#pragma unroll
        for (int o = 16; o > 0; o >>= 1) s += __shfl_xor_sync(0xffffffffu, s, o);
        if (lane == 0) y1_s[j] = fmaxf(s + __ldg(b1 + j), 0.f);
    }
    __syncthreads();

    if (tid < 144) {
        const int r = cg * 144 + tid;
        float a = __ldg(b2 + r);
        const float* row = w2c + tid * MID;
#pragma unroll
        for (int m = 0; m < MID; m++) a = fmaf(y1_s[m], row[m], a);
        y2_s[tid] = a;
    }
    __syncthreads();

    if (tid < 16) {
        const int c = cg * 16 + tid;
        float y[TAPS];
        float m = 0.f;
#pragma unroll
        for (int k = 0; k < TAPS; k++) { y[k] = y2_s[tid * TAPS + k]; m += y[k]; }
        m *= (1.f / 9.f);
        float ss = 0.f;
#pragma unroll
        for (int k = 0; k < TAPS; k++) { float d = y[k] - m; ss = fmaf(d, d, ss); }
        float inv = 1.f / (sqrtf(ss * (1.f / 8.f)) + 1e-10f);
#pragma unroll
        for (int k = 0; k < TAPS; k++)
            g_cf[(size_t)b * CKK + c * TAPS + k] =
                (y[k] - m) * inv * __ldg(fn_std + c * TAPS + k);
    }
}

// ---------------------------------------------------------------------------
// Kernel 3 (R6 proven CG16 f32x2): PDL secondary. x-halo loads issued BEFORE
// gdc_wait (depend only on input x); sf/cf read after.
// ---------------------------------------------------------------------------
#define K3_CG 16
#define HSTR 60
#define HSZ  (10 * HSTR)
__global__ void __launch_bounds__(224) k3_ddf(
    const float* __restrict__ x, float* __restrict__ out)
{
    __shared__ __align__(16) float xh[K3_CG * HSZ];       // 38.4 KB
    __shared__ __align__(16) ull cf2_s[K3_CG * TAPS];

    const int b  = blockIdx.z;
    const int cg = blockIdx.y;
    const int r0 = blockIdx.x * 8;
    const int tx = threadIdx.x;
    const int ty = threadIdx.y;
    const int tid = ty * 28 + tx;

    const int row = r0 + ty;
    const int col = 2 * tx;

    // channel-invariant halo slots
    int  idx[3]; const float* ptr[3]; bool vld[3], has[3];
#pragma unroll
    for (int s = 0; s < 3; s++) {
        int i = tid + s * 224;
        has[s] = (i < 580);
        int ii = has[s] ? i : 0;
        int rr = ii / 58, jj = ii % 58;
        int gr = r0 - 1 + rr, gc = jj - 1;
        vld[s] = has[s] && (gr >= 0) && (gr < HH) && (gc >= 0) && (gc < WW);
        idx[s] = rr * HSTR + jj;
        ptr[s] = x + ((size_t)b * CC + cg * K3_CG) * HW + gr * WW + gc;
    }

    // x halo loads: depend only on input x -> before gdc_wait
#pragma unroll
    for (int g = 0; g < K3_CG; g++) {
#pragma unroll
        for (int s = 0; s < 3; s++) {
            float v = vld[s] ? __ldg(ptr[s] + (size_t)g * HW) : 0.f;
            if (has[s]) xh[g * HSZ + idx[s]] = v;
        }
    }

    gdc_wait();                               // k2's g_cf (and kA's g_sf) visible

    if (tid < K3_CG * TAPS) {
        float v = g_cf[(size_t)b * CKK + cg * K3_CG * TAPS + tid];
        cf2_s[tid] = pack2(v, v);
    }

    ull sfr[TAPS];
    {
        const float* sp = g_sf + (size_t)b * TAPS * HW + row * WW + col;
#pragma unroll
        for (int n = 0; n < TAPS; n++)
            sfr[n] = __ldg((const ull*)(sp + n * HW));
    }
    __syncthreads();

    const float* hbase = xh + ty * HSTR + col;
    float* po = out + ((size_t)b * CC + cg * K3_CG) * HW + row * WW + col;

#pragma unroll
    for (int g = 0; g < K3_CG; g++) {
        const float* hp = hbase + g * HSZ;
        ull acc = 0ULL;
        const ull* cfp = cf2_s + g * TAPS;

#pragma unroll
        for (int u = 0; u < KK; u++) {
            ull A = *(const ull*)(hp + u * HSTR);
            ull B = *(const ull*)(hp + u * HSTR + 2);
            float alo, ahi, blo, bhi;
            unpack2(A, alo, ahi);
            unpack2(B, blo, bhi);
            ull M = pack2(ahi, blo);
            acc = fma2(A, mul2(cfp[u * 3 + 0], sfr[u * 3 + 0]), acc);
            acc = fma2(M, mul2(cfp[u * 3 + 1], sfr[u * 3 + 1]), acc);
            acc = fma2(B, mul2(cfp[u * 3 + 2], sfr[u * 3 + 2]), acc);
        }

        *(ull*)po = acc;
        po += HW;
    }
}

// ---------------------------------------------------------------------------
extern "C" void kernel_launch(void* const* d_in, const int* in_sizes, int n_in,
                              void* d_out, int out_size)
{
    const float* x      = (const float*)d_in[0];
    const float* w1     = (const float*)d_in[1];
    const float* b1     = (const float*)d_in[2];
    const float* w2     = (const float*)d_in[3];
    const float* b2     = (const float*)d_in[4];
    const float* ws     = (const float*)d_in[5];
    const float* bs     = (const float*)d_in[6];
    const float* fn_std = (const float*)d_in[7];
    float* out = (float*)d_out;

    // kA: primary
    dim3 gA(98 + 16, BB);
    kA_sf_pool<<<gA, 512>>>(x, ws, bs);

    cudaLaunchAttribute pdl[1];
    pdl[0].id = cudaLaunchAttributeProgrammaticStreamSerialization;
    pdl[0].val.programmaticStreamSerializationAllowed = 1;

    // k2: PDL secondary of kA
    {
        cudaLaunchConfig_t cfg = {};
        cfg.gridDim  = dim3(16, BB);
        cfg.blockDim = dim3(256);
        cfg.stream   = 0;
        cfg.attrs    = pdl;
        cfg.numAttrs = 1;
        cudaLaunchKernelEx(&cfg, k2_mlp_cf, w1, b1, w2, b2, fn_std);
    }

    // k3: PDL secondary of k2
    {
        cudaLaunchConfig_t cfg = {};
        cfg.gridDim  = dim3(HH / 8, CC / K3_CG, BB);
        cfg.blockDim = dim3(28, 8);
        cfg.stream   = 0;
        cfg.attrs    = pdl;
        cfg.numAttrs = 1;
        cudaLaunchKernelEx(&cfg, k3_ddf, x, out);
    }
}

// round 10
// speedup vs baseline: 1.1021x; 1.1021x over previous
#include <cuda_runtime.h>
#include <math.h>

#define BB 8
#define CC 256
#define HH 56
#define WW 56
#define HW (HH*WW)          // 3136
#define KK 3
#define TAPS 9
#define MID 51
#define CKK (CC*TAPS)       // 2304
#define GAIN_OVER_K 0.4714045207910317f   // sqrt(2)/3

__device__ float g_pooled[BB * CC];
__device__ float g_sf[BB * TAPS * HW];
__device__ float g_cf[BB * CKK];

typedef unsigned long long ull;

// ---- f32x2 packed helpers (sm_103a) --------------------------------------
__device__ __forceinline__ ull pack2(float x, float y) {
    ull r; asm("mov.b64 %0, {%1, %2};" : "=l"(r) : "f"(x), "f"(y)); return r;
}
__device__ __forceinline__ void unpack2(ull v, float& x, float& y) {
    asm("mov.b64 {%0, %1}, %2;" : "=f"(x), "=f"(y) : "l"(v));
}
__device__ __forceinline__ ull mul2(ull a, ull b) {
    ull d; asm("mul.rn.f32x2 %0, %1, %2;" : "=l"(d) : "l"(a), "l"(b)); return d;
}
__device__ __forceinline__ ull fma2(ull a, ull b, ull c) {
    ull d; asm("fma.rn.f32x2 %0, %1, %2, %3;" : "=l"(d) : "l"(a), "l"(b), "l"(c)); return d;
}

// ---------------------------------------------------------------------------
// Kernel A: single-wave layout (520 blocks, 4 CTAs/SM -> 592 slots).
//   bx < 49 : sf for a 64-px tile. Warp w: channels [(w&7)*32, +32),
//             pixels [bx*64 + (w>>3)*32 + lane].
//   bx >= 49: pooled means, warp per channel (16 channels per block).
// ---------------------------------------------------------------------------
__global__ void __launch_bounds__(512, 4) kA_sf_pool(
    const float* __restrict__ x,
    const float* __restrict__ ws,
    const float* __restrict__ bs)
{
    __shared__ float ws_s[CC * 12];           // 12 KB
    __shared__ float red[8 * TAPS * 64];      // 18 KB

    const int b    = blockIdx.y;
    const int bx   = blockIdx.x;
    const int tid  = threadIdx.x;
    const int lane = tid & 31;
    const int w    = tid >> 5;

    if (bx >= 49) {
        const int c = (bx - 49) * 16 + w;
        const float4* p4 = (const float4*)(x + ((size_t)b * CC + c) * HW);
        float s = 0.f;
        for (int j = lane; j < 784; j += 32) {
            float4 v = __ldg(p4 + j);
            s += (v.x + v.y) + (v.z + v.w);
        }
#pragma unroll
        for (int o = 16; o > 0; o >>= 1) s += __shfl_xor_sync(0xffffffffu, s, o);
        if (lane == 0) g_pooled[b * CC + c] = s * (1.f / (float)HW);
        return;
    }

#pragma unroll
    for (int i = tid; i < TAPS * CC; i += 512) {
        int n = i >> 8, c = i & 255;
        ws_s[c * 12 + n] = ws[i];
    }
    __syncthreads();

    const int cg   = w & 7;                   // channel group (32 ch)
    const int half = w >> 3;                  // pixel half (0/1)
    const int p    = half * 32 + lane;        // pixel within 64-px tile
    const int pix  = bx * 64 + p;             // always < HW
    const float* xb = x + ((size_t)b * CC + cg * 32) * HW + pix;

    float acc[TAPS];
#pragma unroll
    for (int n = 0; n < TAPS; n++) acc[n] = 0.f;

#pragma unroll 8
    for (int cc = 0; cc < 32; cc++) {
        float xv = __ldg(xb + (size_t)cc * HW);
        const float* wr = ws_s + (cg * 32 + cc) * 12;
        float4 wa = *(const float4*)(wr);
        float4 wb = *(const float4*)(wr + 4);
        float  w8 = wr[8];
        acc[0] = fmaf(xv, wa.x, acc[0]);
        acc[1] = fmaf(xv, wa.y, acc[1]);
        acc[2] = fmaf(xv, wa.z, acc[2]);
        acc[3] = fmaf(xv, wa.w, acc[3]);
        acc[4] = fmaf(xv, wb.x, acc[4]);
        acc[5] = fmaf(xv, wb.y, acc[5]);
        acc[6] = fmaf(xv, wb.z, acc[6]);
        acc[7] = fmaf(xv, wb.w, acc[7]);
        acc[8] = fmaf(xv, w8,   acc[8]);
    }

#pragma unroll
    for (int n = 0; n < TAPS; n++)
        red[(cg * TAPS + n) * 64 + p] = acc[n];
    __syncthreads();

    if (tid < 64) {
        float a[TAPS];
        float m = 0.f;
#pragma unroll
        for (int n = 0; n < TAPS; n++) {
            float s = 0.f;
#pragma unroll
            for (int gg = 0; gg < 8; gg++) s += red[(gg * TAPS + n) * 64 + tid];
            a[n] = s + __ldg(bs + n);
            m += a[n];
        }
        m *= (1.f / 9.f);
        float ss = 0.f;
#pragma unroll
        for (int n = 0; n < TAPS; n++) { float d = a[n] - m; ss = fmaf(d, d, ss); }
        float inv = GAIN_OVER_K / (sqrtf(ss * (1.f / 8.f)) + 1e-10f);
        const int pix2 = bx * 64 + tid;
#pragma unroll
        for (int n = 0; n < TAPS; n++)
            g_sf[((size_t)b * TAPS + n) * HW + pix2] = (a[n] - m) * inv;
    }
}

// ---------------------------------------------------------------------------
// Kernel 2 (exact R6): MLP + per-channel normalize -> cf.
// ---------------------------------------------------------------------------
__global__ void __launch_bounds__(256) k2_mlp_cf(
    const float* __restrict__ w1, const float* __restrict__ b1,
    const float* __restrict__ w2, const float* __restrict__ b2,
    const float* __restrict__ fn_std)
{
    __shared__ float pooled_s[CC];
    __shared__ float y1_s[52];
    __shared__ float w2c[144 * MID];
    __shared__ float y2_s[144];

    const int cg   = blockIdx.x;
    const int b    = blockIdx.y;
    const int tid  = threadIdx.x;
    const int warp = tid >> 5;
    const int lane = tid & 31;

    pooled_s[tid] = g_pooled[b * CC + tid];

    {
        const float4* src = (const float4*)(w2 + (size_t)cg * 144 * MID);
#pragma unroll
        for (int i = tid; i < 144 * MID / 4; i += 256)
            ((float4*)w2c)[i] = __ldg(src + i);
    }
    __syncthreads();

    for (int j = warp; j < MID; j += 8) {
        const float* wr = w1 + j * CC;
        float s = 0.f;
#pragma unroll
        for (int k = 0; k < CC / 32; k++)
            s = fmaf(pooled_s[lane + k * 32], __ldg(wr + lane + k * 32), s);
#pragma unroll
        for (int o = 16; o > 0; o >>= 1) s += __shfl_xor_sync(0xffffffffu, s, o);
        if (lane == 0) y1_s[j] = fmaxf(s + __ldg(b1 + j), 0.f);
    }
    __syncthreads();

    if (tid < 144) {
        const int r = cg * 144 + tid;
        float a = __ldg(b2 + r);
        const float* row = w2c + tid * MID;
#pragma unroll
        for (int m = 0; m < MID; m++) a = fmaf(y1_s[m], row[m], a);
        y2_s[tid] = a;
    }
    __syncthreads();

    if (tid < 16) {
        const int c = cg * 16 + tid;
        float y[TAPS];
        float m = 0.f;
#pragma unroll
        for (int k = 0; k < TAPS; k++) { y[k] = y2_s[tid * TAPS + k]; m += y[k]; }
        m *= (1.f / 9.f);
        float ss = 0.f;
#pragma unroll
        for (int k = 0; k < TAPS; k++) { float d = y[k] - m; ss = fmaf(d, d, ss); }
        float inv = 1.f / (sqrtf(ss * (1.f / 8.f)) + 1e-10f);
#pragma unroll
        for (int k = 0; k < TAPS; k++)
            g_cf[(size_t)b * CKK + c * TAPS + k] =
                (y[k] - m) * inv * __ldg(fn_std + c * TAPS + k);
    }
}

// ---------------------------------------------------------------------------
// Kernel 3 (exact R6): DDF combine, f32x2, 16 channels per block.
// ---------------------------------------------------------------------------
#define K3_CG 16
#define HSTR 60
#define HSZ  (10 * HSTR)
__global__ void __launch_bounds__(224) k3_ddf(
    const float* __restrict__ x, float* __restrict__ out)
{
    __shared__ __align__(16) float xh[K3_CG * HSZ];       // 38.4 KB
    __shared__ __align__(16) ull cf2_s[K3_CG * TAPS];

    const int b  = blockIdx.z;
    const int cg = blockIdx.y;
    const int r0 = blockIdx.x * 8;
    const int tx = threadIdx.x;
    const int ty = threadIdx.y;
    const int tid = ty * 28 + tx;

    const int row = r0 + ty;
    const int col = 2 * tx;

    if (tid < K3_CG * TAPS) {
        float v = g_cf[(size_t)b * CKK + cg * K3_CG * TAPS + tid];
        cf2_s[tid] = pack2(v, v);
    }

    ull sfr[TAPS];
    {
        const float* sp = g_sf + (size_t)b * TAPS * HW + row * WW + col;
#pragma unroll
        for (int n = 0; n < TAPS; n++)
            sfr[n] = __ldg((const ull*)(sp + n * HW));
    }

    int  idx[3]; const float* ptr[3]; bool vld[3], has[3];
#pragma unroll
    for (int s = 0; s < 3; s++) {
        int i = tid + s * 224;
        has[s] = (i < 580);
        int ii = has[s] ? i : 0;
        int rr = ii / 58, jj = ii % 58;
        int gr = r0 - 1 + rr, gc = jj - 1;
        vld[s] = has[s] && (gr >= 0) && (gr < HH) && (gc >= 0) && (gc < WW);
        idx[s] = rr * HSTR + jj;
        ptr[s] = x + ((size_t)b * CC + cg * K3_CG) * HW + gr * WW + gc;
    }

#pragma unroll
    for (int g = 0; g < K3_CG; g++) {
#pragma unroll
        for (int s = 0; s < 3; s++) {
            float v = vld[s] ? __ldg(ptr[s] + (size_t)g * HW) : 0.f;
            if (has[s]) xh[g * HSZ + idx[s]] = v;
        }
    }
    __syncthreads();

    const float* hbase = xh + ty * HSTR + col;
    float* po = out + ((size_t)b * CC + cg * K3_CG) * HW + row * WW + col;

#pragma unroll
    for (int g = 0; g < K3_CG; g++) {
        const float* hp = hbase + g * HSZ;
        ull acc = 0ULL;
        const ull* cfp = cf2_s + g * TAPS;

#pragma unroll
        for (int u = 0; u < KK; u++) {
            ull A = *(const ull*)(hp + u * HSTR);
            ull B = *(const ull*)(hp + u * HSTR + 2);
            float alo, ahi, blo, bhi;
            unpack2(A, alo, ahi);
            unpack2(B, blo, bhi);
            ull M = pack2(ahi, blo);
            acc = fma2(A, mul2(cfp[u * 3 + 0], sfr[u * 3 + 0]), acc);
            acc = fma2(M, mul2(cfp[u * 3 + 1], sfr[u * 3 + 1]), acc);
            acc = fma2(B, mul2(cfp[u * 3 + 2], sfr[u * 3 + 2]), acc);
        }

        *(ull*)po = acc;
        po += HW;
    }
}

// ---------------------------------------------------------------------------
extern "C" void kernel_launch(void* const* d_in, const int* in_sizes, int n_in,
                              void* d_out, int out_size)
{
    const float* x      = (const float*)d_in[0];
    const float* w1     = (const float*)d_in[1];
    const float* b1     = (const float*)d_in[2];
    const float* w2     = (const float*)d_in[3];
    const float* b2     = (const float*)d_in[4];
    const float* ws     = (const float*)d_in[5];
    const float* bs     = (const float*)d_in[6];
    const float* fn_std = (const float*)d_in[7];
    float* out = (float*)d_out;

    dim3 gA(49 + 16, BB);            // 520 blocks -> single wave at 4 CTAs/SM
    kA_sf_pool<<<gA, 512>>>(x, ws, bs);

    dim3 g2(16, BB);
    k2_mlp_cf<<<g2, 256>>>(w1, b1, w2, b2, fn_std);

    dim3 g3(HH / 8, CC / K3_CG, BB);
    dim3 b3(28, 8);
    k3_ddf<<<g3, b3>>>(x, out);
}